// round 10
// baseline (speedup 1.0000x reference)
#include <cuda_runtime.h>
#include <cuda_bf16.h>
#include <cstdint>

// Problem constants (fixed by the reference)
constexpr int NN   = 50000;
constexpr int EE   = 800000;
constexpr int DIN  = 128;
constexpr int DHID = 256;
constexpr int SCAN_B = 256;
constexpr int NBLK   = (NN + SCAN_B - 1) / SCAN_B;   // 196

// ---------------- scratch (device globals: allocation-free) ----------------
__device__ __align__(16) float g_deg  [NN];
__device__ __align__(16) float g_dinv [NN];
__device__ __align__(16) int   g_cnt  [NN];
__device__ __align__(16) int   g_cur  [NN];
__device__ __align__(16) int   g_scan [NN];
__device__ __align__(16) int   g_bsum [SCAN_B];
__device__ __align__(16) int   g_rowptr[NN + 1];
__device__ __align__(16) int   g_esrc [EE];
__device__ __align__(16) float g_enorm[EE];
__device__ __align__(16) float g_aggx [(size_t)NN * DIN];    // S @ x
__device__ __align__(16) float g_out1 [(size_t)NN * DHID];   // relu(aggx @ W1^T + b1)
__device__ __align__(16) float g_h2   [(size_t)NN * DIN];    // out1 @ W2^T

// ---------------- normalization coefficient kernels ----------------
__global__ void deg_init_kernel(float* deg, int* cnt, int* cur, int n) {
    int i = blockIdx.x * blockDim.x + threadIdx.x;
    if (i < n) { deg[i] = 1.0f; cnt[i] = 0; cur[i] = 0; }
}

__global__ void deg_acc_kernel(const int* __restrict__ dst,
                               const float* __restrict__ w,
                               float* deg, int* cnt, int e) {
    int i = blockIdx.x * blockDim.x + threadIdx.x;
    if (i < e) {
        int d = dst[i];
        atomicAdd(&deg[d], w[i]);
        atomicAdd(&cnt[d], 1);
    }
}

__global__ void dinv_kernel(const float* __restrict__ deg, float* dinv, int n) {
    int i = blockIdx.x * blockDim.x + threadIdx.x;
    if (i < n) dinv[i] = rsqrtf(deg[i]);
}

// ---------------- CSR build: 2-level scan + cursor fill (norm fused) ----------------
__global__ void scan_block_kernel(const int* __restrict__ cnt,
                                  int* __restrict__ scan,
                                  int* __restrict__ bsum, int n) {
    __shared__ int sh[SCAN_B];
    int i = blockIdx.x * SCAN_B + threadIdx.x;
    sh[threadIdx.x] = (i < n) ? cnt[i] : 0;
    __syncthreads();
    #pragma unroll
    for (int o = 1; o < SCAN_B; o <<= 1) {
        int t = (threadIdx.x >= o) ? sh[threadIdx.x - o] : 0;
        __syncthreads();
        sh[threadIdx.x] += t;
        __syncthreads();
    }
    if (i < n) scan[i] = sh[threadIdx.x];
    if (threadIdx.x == SCAN_B - 1) bsum[blockIdx.x] = sh[SCAN_B - 1];
}

__global__ void scan_bsum_kernel(int* __restrict__ bsum, int nb) {
    __shared__ int sh[SCAN_B];
    sh[threadIdx.x] = (threadIdx.x < nb) ? bsum[threadIdx.x] : 0;
    __syncthreads();
    #pragma unroll
    for (int o = 1; o < SCAN_B; o <<= 1) {
        int t = (threadIdx.x >= o) ? sh[threadIdx.x - o] : 0;
        __syncthreads();
        sh[threadIdx.x] += t;
        __syncthreads();
    }
    if (threadIdx.x < nb) bsum[threadIdx.x] = sh[threadIdx.x];
}

__global__ void rowptr_kernel(const int* __restrict__ scan,
                              const int* __restrict__ bsum,
                              int* __restrict__ rowptr, int n) {
    int i = blockIdx.x * SCAN_B + threadIdx.x;
    if (i < n) {
        int off = (blockIdx.x > 0) ? bsum[blockIdx.x - 1] : 0;
        rowptr[i + 1] = scan[i] + off;
    }
    if (i == 0) rowptr[0] = 0;
}

// norm computed inline: enorm = dinv[src]*w*dinv[dst]
__global__ void fill_kernel(const int* __restrict__ src,
                            const int* __restrict__ dst,
                            const float* __restrict__ w,
                            const float* __restrict__ dinv,
                            const int* __restrict__ rowptr,
                            int* __restrict__ cur,
                            int* __restrict__ esrc,
                            float* __restrict__ enorm, int e) {
    int i = blockIdx.x * blockDim.x + threadIdx.x;
    if (i < e) {
        int s = src[i];
        int d = dst[i];
        int p = rowptr[d] + atomicAdd(&cur[d], 1);
        esrc[p]  = s;
        enorm[p] = dinv[s] * w[i] * dinv[d];
    }
}

// ---------------- D=128 gather: aggx = dinv^2*x_i + sum norm*x[src] ----------------
__global__ __launch_bounds__(256)
void gather0_kernel(const float* __restrict__ x,
                    const int* __restrict__ rowptr,
                    const int* __restrict__ esrc,
                    const float* __restrict__ enorm,
                    const float* __restrict__ dinv,
                    float* __restrict__ out, int n) {
    int node = blockIdx.x * (blockDim.x >> 5) + (threadIdx.x >> 5);
    int lane = threadIdx.x & 31;
    if (node >= n) return;

    const float4* xp = reinterpret_cast<const float4*>(x);
    float s = dinv[node]; s *= s;

    float4 a = xp[(size_t)node * 32 + lane];
    a.x *= s; a.y *= s; a.z *= s; a.w *= s;

    int beg = rowptr[node], end = rowptr[node + 1];
    for (int e = beg; e < end; e++) {
        int   si = esrc[e];
        float w  = enorm[e];
        float4 v = xp[(size_t)si * 32 + lane];
        a.x += w * v.x; a.y += w * v.y; a.z += w * v.z; a.w += w * v.w;
    }
    reinterpret_cast<float4*>(out)[(size_t)node * 32 + lane] = a;
}

// ---------------- 3xTF32 tensor-core GEMM: C = A[M,K] @ B[Ncols,K]^T ----------------
// BM=BN=128, BK=16, 256 threads (8 warps, 4m x 2n), warp tile 32x64.
// Fragment-major smem: conflict-free LDS.128 (A) / LDS.64 (B) fragment loads.
// 3xTF32: a=ah+al, b=bh+bl; ab ~= ah*bh + ah*bl + al*bh (error ~2^-22).
__device__ __forceinline__ uint32_t tf32_cvt(float x) {
    uint32_t u;
    asm("cvt.rna.tf32.f32 %0, %1;" : "=r"(u) : "f"(x));
    return u;
}

__device__ __forceinline__ void mma_tf32(float* d, const uint32_t* a, const uint32_t* b) {
    asm volatile(
        "mma.sync.aligned.m16n8k8.row.col.f32.tf32.tf32.f32 "
        "{%0,%1,%2,%3},{%4,%5,%6,%7},{%8,%9},{%0,%1,%2,%3};"
        : "+f"(d[0]), "+f"(d[1]), "+f"(d[2]), "+f"(d[3])
        : "r"(a[0]), "r"(a[1]), "r"(a[2]), "r"(a[3]), "r"(b[0]), "r"(b[1]));
}

template<bool BIAS_RELU>
__global__ __launch_bounds__(256)
void gemm_tf32_kernel(const float* __restrict__ A, const float* __restrict__ B,
                      const float* __restrict__ bias,
                      float* __restrict__ C, int M, int Ncols, int K) {
    constexpr int BM = 128, BK = 16;
    // [kt][tile][lane][reg]
    __shared__ uint32_t Ah[2][8][32][4], Al[2][8][32][4];
    __shared__ uint32_t Bh[2][16][32][2], Bl[2][16][32][2];

    int tid  = threadIdx.x;
    int lane = tid & 31;
    int warp = tid >> 5;
    int wm = (warp >> 1) * 32;       // warp m-offset within block (0,32,64,96)
    int wn = (warp & 1) * 64;        // warp n-offset within block (0,64)
    int block_row = blockIdx.y * BM;
    int block_col = blockIdx.x * 128;

    int ld_row = tid >> 1;           // 0..127
    int c0     = (tid & 1) * 8;      // 0 or 8

    int a_row = block_row + ld_row;
    bool a_ok = a_row < M;
    const float* a_base = A + (size_t)(a_ok ? a_row : 0) * K + c0;
    const float* b_base = B + (size_t)(block_col + ld_row) * K + c0;

    float d[2][8][4];
    #pragma unroll
    for (int i = 0; i < 2; i++)
        #pragma unroll
        for (int j = 0; j < 8; j++)
            #pragma unroll
            for (int r = 0; r < 4; r++) d[i][j][r] = 0.0f;

    int a_mt = ld_row >> 4, a_ml = ld_row & 15;      // writer A tile / local row
    int b_nt = ld_row >> 3, b_nl = ld_row & 7;       // writer B tile / local col

    for (int k0 = 0; k0 < K; k0 += BK) {
        // global loads (overlap with previous compute)
        float4 av0 = make_float4(0.f,0.f,0.f,0.f), av1 = av0;
        if (a_ok) {
            av0 = *reinterpret_cast<const float4*>(a_base + k0);
            av1 = *reinterpret_cast<const float4*>(a_base + k0 + 4);
        }
        float4 bv0 = *reinterpret_cast<const float4*>(b_base + k0);
        float4 bv1 = *reinterpret_cast<const float4*>(b_base + k0 + 4);

        __syncthreads();   // previous compute done: safe to overwrite frags

        // scatter-store A fragments (8 elems, cols c0..c0+7)
        float ae[8] = {av0.x, av0.y, av0.z, av0.w, av1.x, av1.y, av1.z, av1.w};
        #pragma unroll
        for (int j = 0; j < 8; j++) {
            int kk = c0 + j;
            int kt = kk >> 3, k = kk & 7;
            int lw  = ((a_ml & 7) << 2) | (k & 3);
            int reg = ((k & 4) ? 2 : 0) | ((a_ml & 8) ? 1 : 0);
            uint32_t h = tf32_cvt(ae[j]);
            float    l = ae[j] - __uint_as_float(h);
            Ah[kt][a_mt][lw][reg] = h;
            Al[kt][a_mt][lw][reg] = tf32_cvt(l);
        }
        // scatter-store B fragments
        float be[8] = {bv0.x, bv0.y, bv0.z, bv0.w, bv1.x, bv1.y, bv1.z, bv1.w};
        #pragma unroll
        for (int j = 0; j < 8; j++) {
            int kk = c0 + j;
            int kt = kk >> 3, k = kk & 7;
            int lw  = (b_nl << 2) | (k & 3);
            int reg = (k & 4) ? 1 : 0;
            uint32_t h = tf32_cvt(be[j]);
            float    l = be[j] - __uint_as_float(h);
            Bh[kt][b_nt][lw][reg] = h;
            Bl[kt][b_nt][lw][reg] = tf32_cvt(l);
        }
        __syncthreads();

        // compute 2 k-tiles
        #pragma unroll
        for (int kt = 0; kt < 2; kt++) {
            uint32_t ah[2][4], al[2][4], bh[8][2], bl[8][2];
            #pragma unroll
            for (int mt = 0; mt < 2; mt++) {
                int m = (wm >> 4) + mt;
                *reinterpret_cast<uint4*>(ah[mt]) = *reinterpret_cast<const uint4*>(Ah[kt][m][lane]);
                *reinterpret_cast<uint4*>(al[mt]) = *reinterpret_cast<const uint4*>(Al[kt][m][lane]);
            }
            #pragma unroll
            for (int nt = 0; nt < 8; nt++) {
                int nn = (wn >> 3) + nt;
                *reinterpret_cast<uint2*>(bh[nt]) = *reinterpret_cast<const uint2*>(Bh[kt][nn][lane]);
                *reinterpret_cast<uint2*>(bl[nt]) = *reinterpret_cast<const uint2*>(Bl[kt][nn][lane]);
            }
            #pragma unroll
            for (int mt = 0; mt < 2; mt++)
                #pragma unroll
                for (int nt = 0; nt < 8; nt++) {
                    mma_tf32(d[mt][nt], ah[mt], bh[nt]);
                    mma_tf32(d[mt][nt], ah[mt], bl[nt]);
                    mma_tf32(d[mt][nt], al[mt], bh[nt]);
                }
        }
    }

    // epilogue: c0=(g,2c) c1=(g,2c+1) c2=(g+8,2c) c3=(g+8,2c+1)
    int g = lane >> 2, c = lane & 3;
    #pragma unroll
    for (int mt = 0; mt < 2; mt++) {
        int row0 = block_row + wm + mt * 16 + g;
        int row1 = row0 + 8;
        #pragma unroll
        for (int nt = 0; nt < 8; nt++) {
            int col = block_col + wn + nt * 8 + c * 2;
            float v0 = d[mt][nt][0], v1 = d[mt][nt][1];
            float v2 = d[mt][nt][2], v3 = d[mt][nt][3];
            if (BIAS_RELU) {
                float bb0 = bias[col], bb1 = bias[col + 1];
                v0 = fmaxf(v0 + bb0, 0.f); v1 = fmaxf(v1 + bb1, 0.f);
                v2 = fmaxf(v2 + bb0, 0.f); v3 = fmaxf(v3 + bb1, 0.f);
            }
            if (row0 < M)
                *reinterpret_cast<float2*>(C + (size_t)row0 * Ncols + col) = make_float2(v0, v1);
            if (row1 < M)
                *reinterpret_cast<float2*>(C + (size_t)row1 * Ncols + col) = make_float2(v2, v3);
        }
    }
}

// ---------------- layer-2 gather + fused LayerNorm ----------------
__global__ __launch_bounds__(256)
void gather2_ln_kernel(const float* __restrict__ h,
                       const int* __restrict__ rowptr,
                       const int* __restrict__ esrc,
                       const float* __restrict__ enorm,
                       const float* __restrict__ dinv,
                       const float* __restrict__ bias,
                       const float* __restrict__ gamma,
                       const float* __restrict__ beta,
                       float* __restrict__ out, int n) {
    int node = blockIdx.x * (blockDim.x >> 5) + (threadIdx.x >> 5);
    int lane = threadIdx.x & 31;
    if (node >= n) return;

    const float4* hp = reinterpret_cast<const float4*>(h);
    float s = dinv[node]; s *= s;

    float4 a = hp[(size_t)node * 32 + lane];
    float4 bv = reinterpret_cast<const float4*>(bias)[lane];
    a.x = a.x * s + bv.x; a.y = a.y * s + bv.y;
    a.z = a.z * s + bv.z; a.w = a.w * s + bv.w;

    int beg = rowptr[node], end = rowptr[node + 1];
    for (int e = beg; e < end; e++) {
        int   si = esrc[e];
        float w  = enorm[e];
        float4 v = hp[(size_t)si * 32 + lane];
        a.x += w * v.x; a.y += w * v.y; a.z += w * v.z; a.w += w * v.w;
    }

    float sum = a.x + a.y + a.z + a.w;
    #pragma unroll
    for (int o = 16; o; o >>= 1) sum += __shfl_xor_sync(0xFFFFFFFFu, sum, o);
    float mu = sum * (1.0f / 128.0f);
    float dx = a.x - mu, dy = a.y - mu, dz = a.z - mu, dw = a.w - mu;
    float sq = dx * dx + dy * dy + dz * dz + dw * dw;
    #pragma unroll
    for (int o = 16; o; o >>= 1) sq += __shfl_xor_sync(0xFFFFFFFFu, sq, o);
    float inv = rsqrtf(sq * (1.0f / 128.0f) + 1e-5f);

    float4 gm = reinterpret_cast<const float4*>(gamma)[lane];
    float4 bt = reinterpret_cast<const float4*>(beta)[lane];
    float4 o4;
    o4.x = dx * inv * gm.x + bt.x;
    o4.y = dy * inv * gm.y + bt.y;
    o4.z = dz * inv * gm.z + bt.z;
    o4.w = dw * inv * gm.w + bt.w;
    reinterpret_cast<float4*>(out)[(size_t)node * 32 + lane] = o4;
}

// ---------------- host launcher ----------------
extern "C" void kernel_launch(void* const* d_in, const int* in_sizes, int n_in,
                              void* d_out, int out_size) {
    const float* x     = (const float*)d_in[0];
    const int*   ei    = (const int*)d_in[1];   // int32 (JAX x64 disabled)
    const float* w     = (const float*)d_in[2];
    const float* W1    = (const float*)d_in[3];
    const float* b1    = (const float*)d_in[4];
    const float* W2    = (const float*)d_in[5];
    const float* b2    = (const float*)d_in[6];
    const float* gamma = (const float*)d_in[7];
    const float* beta  = (const float*)d_in[8];
    float*       out   = (float*)d_out;

    const int* src = ei;
    const int* dst = ei + EE;

    float *deg, *dinv, *aggx, *out1, *h2, *enorm;
    int *cnt, *cur, *scan, *bsum, *rowptr, *esrc;
    cudaGetSymbolAddress((void**)&deg,    g_deg);
    cudaGetSymbolAddress((void**)&dinv,   g_dinv);
    cudaGetSymbolAddress((void**)&cnt,    g_cnt);
    cudaGetSymbolAddress((void**)&cur,    g_cur);
    cudaGetSymbolAddress((void**)&scan,   g_scan);
    cudaGetSymbolAddress((void**)&bsum,   g_bsum);
    cudaGetSymbolAddress((void**)&rowptr, g_rowptr);
    cudaGetSymbolAddress((void**)&esrc,   g_esrc);
    cudaGetSymbolAddress((void**)&enorm,  g_enorm);
    cudaGetSymbolAddress((void**)&aggx,   g_aggx);
    cudaGetSymbolAddress((void**)&out1,   g_out1);
    cudaGetSymbolAddress((void**)&h2,     g_h2);

    const int T = 256;

    // normalization coefficients + histogram
    deg_init_kernel<<<(NN + T - 1) / T, T>>>(deg, cnt, cur, NN);
    deg_acc_kernel<<<(EE + T - 1) / T, T>>>(dst, w, deg, cnt, EE);
    dinv_kernel<<<(NN + T - 1) / T, T>>>(deg, dinv, NN);

    // CSR build (sorted by dst), norm fused into fill
    scan_block_kernel<<<NBLK, SCAN_B>>>(cnt, scan, bsum, NN);
    scan_bsum_kernel<<<1, SCAN_B>>>(bsum, NBLK);
    rowptr_kernel<<<NBLK, SCAN_B>>>(scan, bsum, rowptr, NN);
    fill_kernel<<<(EE + T - 1) / T, T>>>(src, dst, w, dinv, rowptr, cur, esrc, enorm, EE);

    // layer 1 (reordered): aggx = S @ x ; out1 = relu(aggx @ W1^T + b1)
    gather0_kernel<<<(NN + 7) / 8, 256>>>(x, rowptr, esrc, enorm, dinv, aggx, NN);
    {
        dim3 grid(DHID / 128, (NN + 127) / 128);
        gemm_tf32_kernel<true><<<grid, 256>>>(aggx, W1, b1, out1, NN, DHID, DIN);
    }

    // layer 2: h2 = out1 @ W2^T ; out = LN(S @ h2 + b2)
    {
        dim3 grid(DIN / 128, (NN + 127) / 128);
        gemm_tf32_kernel<false><<<grid, 256>>>(out1, W2, nullptr, h2, NN, DIN, DHID);
    }
    gather2_ln_kernel<<<(NN + 7) / 8, 256>>>(h2, rowptr, esrc, enorm, dinv, b2, gamma, beta, out, NN);
}

// round 15
// speedup vs baseline: 1.1637x; 1.1637x over previous
#include <cuda_runtime.h>
#include <cuda_bf16.h>
#include <cstdint>

// Problem constants (fixed by the reference)
constexpr int NN   = 50000;
constexpr int EE   = 800000;
constexpr int DIN  = 128;
constexpr int DHID = 256;
constexpr int SCAN_B = 256;
constexpr int NBLK   = (NN + SCAN_B - 1) / SCAN_B;   // 196

// ---------------- scratch (device globals: allocation-free) ----------------
__device__ __align__(16) float g_deg  [NN];
__device__ __align__(16) float g_dinv [NN];
__device__ __align__(16) int   g_cnt  [NN];
__device__ __align__(16) int   g_cur  [NN];
__device__ __align__(16) int   g_scan [NN];
__device__ __align__(16) int   g_bsum [SCAN_B];
__device__ __align__(16) int   g_rowptr[NN + 1];
__device__ __align__(16) int   g_esrc [EE];
__device__ __align__(16) float g_enorm[EE];
__device__ __align__(16) float g_aggx [(size_t)NN * DIN];    // S @ x
__device__ __align__(16) float g_out1 [(size_t)NN * DHID];   // relu(aggx @ W1^T + b1)
__device__ __align__(16) float g_h2   [(size_t)NN * DIN];    // out1 @ W2^T

// ---------------- normalization coefficient kernels ----------------
__global__ void deg_init_kernel(float* deg, int* cnt, int* cur, int n) {
    int i = blockIdx.x * blockDim.x + threadIdx.x;
    if (i < n) { deg[i] = 1.0f; cnt[i] = 0; cur[i] = 0; }
}

__global__ void deg_acc_kernel(const int* __restrict__ dst,
                               const float* __restrict__ w,
                               float* deg, int* cnt, int e) {
    int i = blockIdx.x * blockDim.x + threadIdx.x;
    if (i < e) {
        int d = dst[i];
        atomicAdd(&deg[d], w[i]);
        atomicAdd(&cnt[d], 1);
    }
}

__global__ void dinv_kernel(const float* __restrict__ deg, float* dinv, int n) {
    int i = blockIdx.x * blockDim.x + threadIdx.x;
    if (i < n) dinv[i] = rsqrtf(deg[i]);
}

// ---------------- CSR build: 2-level scan + cursor fill (norm fused) ----------------
__global__ void scan_block_kernel(const int* __restrict__ cnt,
                                  int* __restrict__ scan,
                                  int* __restrict__ bsum, int n) {
    __shared__ int sh[SCAN_B];
    int i = blockIdx.x * SCAN_B + threadIdx.x;
    sh[threadIdx.x] = (i < n) ? cnt[i] : 0;
    __syncthreads();
    #pragma unroll
    for (int o = 1; o < SCAN_B; o <<= 1) {
        int t = (threadIdx.x >= o) ? sh[threadIdx.x - o] : 0;
        __syncthreads();
        sh[threadIdx.x] += t;
        __syncthreads();
    }
    if (i < n) scan[i] = sh[threadIdx.x];
    if (threadIdx.x == SCAN_B - 1) bsum[blockIdx.x] = sh[SCAN_B - 1];
}

__global__ void scan_bsum_kernel(int* __restrict__ bsum, int nb) {
    __shared__ int sh[SCAN_B];
    sh[threadIdx.x] = (threadIdx.x < nb) ? bsum[threadIdx.x] : 0;
    __syncthreads();
    #pragma unroll
    for (int o = 1; o < SCAN_B; o <<= 1) {
        int t = (threadIdx.x >= o) ? sh[threadIdx.x - o] : 0;
        __syncthreads();
        sh[threadIdx.x] += t;
        __syncthreads();
    }
    if (threadIdx.x < nb) bsum[threadIdx.x] = sh[threadIdx.x];
}

__global__ void rowptr_kernel(const int* __restrict__ scan,
                              const int* __restrict__ bsum,
                              int* __restrict__ rowptr, int n) {
    int i = blockIdx.x * SCAN_B + threadIdx.x;
    if (i < n) {
        int off = (blockIdx.x > 0) ? bsum[blockIdx.x - 1] : 0;
        rowptr[i + 1] = scan[i] + off;
    }
    if (i == 0) rowptr[0] = 0;
}

// norm computed inline: enorm = dinv[src]*w*dinv[dst]
__global__ void fill_kernel(const int* __restrict__ src,
                            const int* __restrict__ dst,
                            const float* __restrict__ w,
                            const float* __restrict__ dinv,
                            const int* __restrict__ rowptr,
                            int* __restrict__ cur,
                            int* __restrict__ esrc,
                            float* __restrict__ enorm, int e) {
    int i = blockIdx.x * blockDim.x + threadIdx.x;
    if (i < e) {
        int s = src[i];
        int d = dst[i];
        int p = rowptr[d] + atomicAdd(&cur[d], 1);
        esrc[p]  = s;
        enorm[p] = dinv[s] * w[i] * dinv[d];
    }
}

// ---------------- D=128 gather (x4 unroll): aggx = dinv^2*x_i + sum norm*x[src] ----
__global__ __launch_bounds__(256)
void gather0_kernel(const float* __restrict__ x,
                    const int* __restrict__ rowptr,
                    const int* __restrict__ esrc,
                    const float* __restrict__ enorm,
                    const float* __restrict__ dinv,
                    float* __restrict__ out, int n) {
    int node = blockIdx.x * (blockDim.x >> 5) + (threadIdx.x >> 5);
    int lane = threadIdx.x & 31;
    if (node >= n) return;

    const float4* xp = reinterpret_cast<const float4*>(x);
    float s = dinv[node]; s *= s;

    float4 a = xp[(size_t)node * 32 + lane];
    a.x *= s; a.y *= s; a.z *= s; a.w *= s;

    int beg = rowptr[node], end = rowptr[node + 1];
    int e = beg;
    for (; e + 4 <= end; e += 4) {
        int   s0 = esrc[e],     s1 = esrc[e + 1], s2 = esrc[e + 2], s3 = esrc[e + 3];
        float w0 = enorm[e],    w1 = enorm[e + 1];
        float w2 = enorm[e + 2], w3 = enorm[e + 3];
        float4 v0 = xp[(size_t)s0 * 32 + lane];
        float4 v1 = xp[(size_t)s1 * 32 + lane];
        float4 v2 = xp[(size_t)s2 * 32 + lane];
        float4 v3 = xp[(size_t)s3 * 32 + lane];
        a.x += w0 * v0.x; a.y += w0 * v0.y; a.z += w0 * v0.z; a.w += w0 * v0.w;
        a.x += w1 * v1.x; a.y += w1 * v1.y; a.z += w1 * v1.z; a.w += w1 * v1.w;
        a.x += w2 * v2.x; a.y += w2 * v2.y; a.z += w2 * v2.z; a.w += w2 * v2.w;
        a.x += w3 * v3.x; a.y += w3 * v3.y; a.z += w3 * v3.z; a.w += w3 * v3.w;
    }
    for (; e < end; e++) {
        int   si = esrc[e];
        float w  = enorm[e];
        float4 v = xp[(size_t)si * 32 + lane];
        a.x += w * v.x; a.y += w * v.y; a.z += w * v.z; a.w += w * v.w;
    }
    reinterpret_cast<float4*>(out)[(size_t)node * 32 + lane] = a;
}

// ---------------- double-buffered SGEMM: C = A[M,K] @ B[Ncols,K]^T (+bias, relu) ----
// BM=BN=128, BK=16, 256 threads, 8x8 microtile, 2-stage smem pipeline.
template<bool BIAS_RELU>
__global__ __launch_bounds__(256)
void sgemm_nt_db_kernel(const float* __restrict__ A, const float* __restrict__ B,
                        const float* __restrict__ bias,
                        float* __restrict__ C, int M, int Ncols, int K) {
    constexpr int BM = 128, BK = 16, TM = 8, TN = 8;
    __shared__ float As[2][BK][BM];
    __shared__ float Bs[2][BK][128];

    int tid = threadIdx.x;
    int tx = tid % 16;
    int ty = tid / 16;
    int block_row = blockIdx.y * BM;
    int block_col = blockIdx.x * 128;

    int ld_row = tid >> 1;          // 0..127
    int c0     = (tid & 1) * 8;     // 0 or 8

    int a_row = block_row + ld_row;
    bool a_ok = a_row < M;
    const float* a_base = A + (size_t)(a_ok ? a_row : 0) * K + c0;
    const float* b_base = B + (size_t)(block_col + ld_row) * K + c0;

    float acc[TM][TN];
    #pragma unroll
    for (int i = 0; i < TM; i++)
        #pragma unroll
        for (int j = 0; j < TN; j++) acc[i][j] = 0.0f;

    // prologue: load tile 0 into buffer 0
    {
        float4 av0 = make_float4(0.f,0.f,0.f,0.f), av1 = make_float4(0.f,0.f,0.f,0.f);
        if (a_ok) {
            av0 = *reinterpret_cast<const float4*>(a_base);
            av1 = *reinterpret_cast<const float4*>(a_base + 4);
        }
        float4 bv0 = *reinterpret_cast<const float4*>(b_base);
        float4 bv1 = *reinterpret_cast<const float4*>(b_base + 4);
        As[0][c0+0][ld_row]=av0.x; As[0][c0+1][ld_row]=av0.y;
        As[0][c0+2][ld_row]=av0.z; As[0][c0+3][ld_row]=av0.w;
        As[0][c0+4][ld_row]=av1.x; As[0][c0+5][ld_row]=av1.y;
        As[0][c0+6][ld_row]=av1.z; As[0][c0+7][ld_row]=av1.w;
        Bs[0][c0+0][ld_row]=bv0.x; Bs[0][c0+1][ld_row]=bv0.y;
        Bs[0][c0+2][ld_row]=bv0.z; Bs[0][c0+3][ld_row]=bv0.w;
        Bs[0][c0+4][ld_row]=bv1.x; Bs[0][c0+5][ld_row]=bv1.y;
        Bs[0][c0+6][ld_row]=bv1.z; Bs[0][c0+7][ld_row]=bv1.w;
    }
    __syncthreads();

    int cur = 0;
    for (int k0 = BK; k0 <= K; k0 += BK) {
        float4 av0, av1, bv0, bv1;
        bool has_next = k0 < K;
        if (has_next) {
            av0 = make_float4(0.f,0.f,0.f,0.f); av1 = av0;
            if (a_ok) {
                av0 = *reinterpret_cast<const float4*>(a_base + k0);
                av1 = *reinterpret_cast<const float4*>(a_base + k0 + 4);
            }
            bv0 = *reinterpret_cast<const float4*>(b_base + k0);
            bv1 = *reinterpret_cast<const float4*>(b_base + k0 + 4);
        }

        #pragma unroll
        for (int kk = 0; kk < BK; kk++) {
            float ar[TM], br[TN];
            #pragma unroll
            for (int i = 0; i < TM; i++) ar[i] = As[cur][kk][ty * TM + i];
            #pragma unroll
            for (int j = 0; j < TN; j++) br[j] = Bs[cur][kk][tx * TN + j];
            #pragma unroll
            for (int i = 0; i < TM; i++)
                #pragma unroll
                for (int j = 0; j < TN; j++)
                    acc[i][j] += ar[i] * br[j];
        }

        if (has_next) {
            int nxt = cur ^ 1;
            As[nxt][c0+0][ld_row]=av0.x; As[nxt][c0+1][ld_row]=av0.y;
            As[nxt][c0+2][ld_row]=av0.z; As[nxt][c0+3][ld_row]=av0.w;
            As[nxt][c0+4][ld_row]=av1.x; As[nxt][c0+5][ld_row]=av1.y;
            As[nxt][c0+6][ld_row]=av1.z; As[nxt][c0+7][ld_row]=av1.w;
            Bs[nxt][c0+0][ld_row]=bv0.x; Bs[nxt][c0+1][ld_row]=bv0.y;
            Bs[nxt][c0+2][ld_row]=bv0.z; Bs[nxt][c0+3][ld_row]=bv0.w;
            Bs[nxt][c0+4][ld_row]=bv1.x; Bs[nxt][c0+5][ld_row]=bv1.y;
            Bs[nxt][c0+6][ld_row]=bv1.z; Bs[nxt][c0+7][ld_row]=bv1.w;
            __syncthreads();
            cur = nxt;
        }
    }

    // epilogue
    float4 bias0 = make_float4(0.f,0.f,0.f,0.f), bias1 = bias0;
    if (BIAS_RELU) {
        const float* bp = bias + block_col + tx * TN;
        bias0 = *reinterpret_cast<const float4*>(bp);
        bias1 = *reinterpret_cast<const float4*>(bp + 4);
    }
    #pragma unroll
    for (int i = 0; i < TM; i++) {
        int gr = block_row + ty * TM + i;
        if (gr < M) {
            float4 c0v = make_float4(acc[i][0], acc[i][1], acc[i][2], acc[i][3]);
            float4 c1v = make_float4(acc[i][4], acc[i][5], acc[i][6], acc[i][7]);
            if (BIAS_RELU) {
                c0v.x = fmaxf(c0v.x + bias0.x, 0.f); c0v.y = fmaxf(c0v.y + bias0.y, 0.f);
                c0v.z = fmaxf(c0v.z + bias0.z, 0.f); c0v.w = fmaxf(c0v.w + bias0.w, 0.f);
                c1v.x = fmaxf(c1v.x + bias1.x, 0.f); c1v.y = fmaxf(c1v.y + bias1.y, 0.f);
                c1v.z = fmaxf(c1v.z + bias1.z, 0.f); c1v.w = fmaxf(c1v.w + bias1.w, 0.f);
            }
            float* cp = C + (size_t)gr * Ncols + block_col + tx * TN;
            *reinterpret_cast<float4*>(cp)     = c0v;
            *reinterpret_cast<float4*>(cp + 4) = c1v;
        }
    }
}

// ---------------- layer-2 gather (x4 unroll) + fused LayerNorm ----------------
__global__ __launch_bounds__(256)
void gather2_ln_kernel(const float* __restrict__ h,
                       const int* __restrict__ rowptr,
                       const int* __restrict__ esrc,
                       const float* __restrict__ enorm,
                       const float* __restrict__ dinv,
                       const float* __restrict__ bias,
                       const float* __restrict__ gamma,
                       const float* __restrict__ beta,
                       float* __restrict__ out, int n) {
    int node = blockIdx.x * (blockDim.x >> 5) + (threadIdx.x >> 5);
    int lane = threadIdx.x & 31;
    if (node >= n) return;

    const float4* hp = reinterpret_cast<const float4*>(h);
    float s = dinv[node]; s *= s;

    float4 a = hp[(size_t)node * 32 + lane];
    float4 bv = reinterpret_cast<const float4*>(bias)[lane];
    a.x = a.x * s + bv.x; a.y = a.y * s + bv.y;
    a.z = a.z * s + bv.z; a.w = a.w * s + bv.w;

    int beg = rowptr[node], end = rowptr[node + 1];
    int e = beg;
    for (; e + 4 <= end; e += 4) {
        int   s0 = esrc[e],     s1 = esrc[e + 1], s2 = esrc[e + 2], s3 = esrc[e + 3];
        float w0 = enorm[e],    w1 = enorm[e + 1];
        float w2 = enorm[e + 2], w3 = enorm[e + 3];
        float4 v0 = hp[(size_t)s0 * 32 + lane];
        float4 v1 = hp[(size_t)s1 * 32 + lane];
        float4 v2 = hp[(size_t)s2 * 32 + lane];
        float4 v3 = hp[(size_t)s3 * 32 + lane];
        a.x += w0 * v0.x; a.y += w0 * v0.y; a.z += w0 * v0.z; a.w += w0 * v0.w;
        a.x += w1 * v1.x; a.y += w1 * v1.y; a.z += w1 * v1.z; a.w += w1 * v1.w;
        a.x += w2 * v2.x; a.y += w2 * v2.y; a.z += w2 * v2.z; a.w += w2 * v2.w;
        a.x += w3 * v3.x; a.y += w3 * v3.y; a.z += w3 * v3.z; a.w += w3 * v3.w;
    }
    for (; e < end; e++) {
        int   si = esrc[e];
        float w  = enorm[e];
        float4 v = hp[(size_t)si * 32 + lane];
        a.x += w * v.x; a.y += w * v.y; a.z += w * v.z; a.w += w * v.w;
    }

    float sum = a.x + a.y + a.z + a.w;
    #pragma unroll
    for (int o = 16; o; o >>= 1) sum += __shfl_xor_sync(0xFFFFFFFFu, sum, o);
    float mu = sum * (1.0f / 128.0f);
    float dx = a.x - mu, dy = a.y - mu, dz = a.z - mu, dw = a.w - mu;
    float sq = dx * dx + dy * dy + dz * dz + dw * dw;
    #pragma unroll
    for (int o = 16; o; o >>= 1) sq += __shfl_xor_sync(0xFFFFFFFFu, sq, o);
    float inv = rsqrtf(sq * (1.0f / 128.0f) + 1e-5f);

    float4 gm = reinterpret_cast<const float4*>(gamma)[lane];
    float4 bt = reinterpret_cast<const float4*>(beta)[lane];
    float4 o4;
    o4.x = dx * inv * gm.x + bt.x;
    o4.y = dy * inv * gm.y + bt.y;
    o4.z = dz * inv * gm.z + bt.z;
    o4.w = dw * inv * gm.w + bt.w;
    reinterpret_cast<float4*>(out)[(size_t)node * 32 + lane] = o4;
}

// ---------------- host launcher ----------------
extern "C" void kernel_launch(void* const* d_in, const int* in_sizes, int n_in,
                              void* d_out, int out_size) {
    const float* x     = (const float*)d_in[0];
    const int*   ei    = (const int*)d_in[1];   // int32 (JAX x64 disabled)
    const float* w     = (const float*)d_in[2];
    const float* W1    = (const float*)d_in[3];
    const float* b1    = (const float*)d_in[4];
    const float* W2    = (const float*)d_in[5];
    const float* b2    = (const float*)d_in[6];
    const float* gamma = (const float*)d_in[7];
    const float* beta  = (const float*)d_in[8];
    float*       out   = (float*)d_out;

    const int* src = ei;
    const int* dst = ei + EE;

    float *deg, *dinv, *aggx, *out1, *h2, *enorm;
    int *cnt, *cur, *scan, *bsum, *rowptr, *esrc;
    cudaGetSymbolAddress((void**)&deg,    g_deg);
    cudaGetSymbolAddress((void**)&dinv,   g_dinv);
    cudaGetSymbolAddress((void**)&cnt,    g_cnt);
    cudaGetSymbolAddress((void**)&cur,    g_cur);
    cudaGetSymbolAddress((void**)&scan,   g_scan);
    cudaGetSymbolAddress((void**)&bsum,   g_bsum);
    cudaGetSymbolAddress((void**)&rowptr, g_rowptr);
    cudaGetSymbolAddress((void**)&esrc,   g_esrc);
    cudaGetSymbolAddress((void**)&enorm,  g_enorm);
    cudaGetSymbolAddress((void**)&aggx,   g_aggx);
    cudaGetSymbolAddress((void**)&out1,   g_out1);
    cudaGetSymbolAddress((void**)&h2,     g_h2);

    const int T = 256;

    // normalization coefficients + histogram
    deg_init_kernel<<<(NN + T - 1) / T, T>>>(deg, cnt, cur, NN);
    deg_acc_kernel<<<(EE + T - 1) / T, T>>>(dst, w, deg, cnt, EE);
    dinv_kernel<<<(NN + T - 1) / T, T>>>(deg, dinv, NN);

    // CSR build (sorted by dst), norm fused into fill
    scan_block_kernel<<<NBLK, SCAN_B>>>(cnt, scan, bsum, NN);
    scan_bsum_kernel<<<1, SCAN_B>>>(bsum, NBLK);
    rowptr_kernel<<<NBLK, SCAN_B>>>(scan, bsum, rowptr, NN);
    fill_kernel<<<(EE + T - 1) / T, T>>>(src, dst, w, dinv, rowptr, cur, esrc, enorm, EE);

    // layer 1 (reordered): aggx = S @ x ; out1 = relu(aggx @ W1^T + b1)
    gather0_kernel<<<(NN + 7) / 8, 256>>>(x, rowptr, esrc, enorm, dinv, aggx, NN);
    {
        dim3 grid(DHID / 128, (NN + 127) / 128);
        sgemm_nt_db_kernel<true><<<grid, 256>>>(aggx, W1, b1, out1, NN, DHID, DIN);
    }

    // layer 2: h2 = out1 @ W2^T ; out = LN(S @ h2 + b2)
    {
        dim3 grid(DIN / 128, (NN + 127) / 128);
        sgemm_nt_db_kernel<false><<<grid, 256>>>(out1, W2, nullptr, h2, NN, DIN, DHID);
    }
    gather2_ln_kernel<<<(NN + 7) / 8, 256>>>(h2, rowptr, esrc, enorm, dinv, b2, gamma, beta, out, NN);
}

// round 17
// speedup vs baseline: 1.4893x; 1.2798x over previous
#include <cuda_runtime.h>
#include <cuda_bf16.h>
#include <cstdint>

// Problem constants (fixed by the reference)
constexpr int NN   = 50000;
constexpr int EE   = 800000;
constexpr int DIN  = 128;
constexpr int DHID = 256;
constexpr int SCAN_B = 256;
constexpr int NBLK   = (NN + SCAN_B - 1) / SCAN_B;   // 196

// ---------------- scratch (device globals: allocation-free) ----------------
__device__ __align__(16) float g_deg  [NN];
__device__ __align__(16) float g_dinv [NN];
__device__ __align__(16) int   g_cnt  [NN];
__device__ __align__(16) int   g_cur  [NN];
__device__ __align__(16) int   g_scan [NN];
__device__ __align__(16) int   g_bsum [SCAN_B];
__device__ __align__(16) int   g_rowptr[NN + 1];
__device__ __align__(16) int   g_esrc [EE];
__device__ __align__(16) float g_enorm[EE];
__device__ __align__(16) float g_aggx [(size_t)NN * DIN];    // S @ x
__device__ __align__(16) float g_out1 [(size_t)NN * DHID];   // relu(aggx @ W1^T + b1)
__device__ __align__(16) float g_h2   [(size_t)NN * DIN];    // out1 @ W2^T

// ---------------- normalization coefficient kernels ----------------
__global__ void deg_init_kernel(float* deg, int* cnt, int* cur, int n) {
    int i = blockIdx.x * blockDim.x + threadIdx.x;
    if (i < n) { deg[i] = 1.0f; cnt[i] = 0; cur[i] = 0; }
}

__global__ void deg_acc_kernel(const int* __restrict__ dst,
                               const float* __restrict__ w,
                               float* deg, int* cnt, int e) {
    int i = blockIdx.x * blockDim.x + threadIdx.x;
    if (i < e) {
        int d = dst[i];
        atomicAdd(&deg[d], w[i]);
        atomicAdd(&cnt[d], 1);
    }
}

__global__ void dinv_kernel(const float* __restrict__ deg, float* dinv, int n) {
    int i = blockIdx.x * blockDim.x + threadIdx.x;
    if (i < n) dinv[i] = rsqrtf(deg[i]);
}

// ---------------- CSR build: 2-level scan + cursor fill (norm fused) ----------------
__global__ void scan_block_kernel(const int* __restrict__ cnt,
                                  int* __restrict__ scan,
                                  int* __restrict__ bsum, int n) {
    __shared__ int sh[SCAN_B];
    int i = blockIdx.x * SCAN_B + threadIdx.x;
    sh[threadIdx.x] = (i < n) ? cnt[i] : 0;
    __syncthreads();
    #pragma unroll
    for (int o = 1; o < SCAN_B; o <<= 1) {
        int t = (threadIdx.x >= o) ? sh[threadIdx.x - o] : 0;
        __syncthreads();
        sh[threadIdx.x] += t;
        __syncthreads();
    }
    if (i < n) scan[i] = sh[threadIdx.x];
    if (threadIdx.x == SCAN_B - 1) bsum[blockIdx.x] = sh[SCAN_B - 1];
}

__global__ void scan_bsum_kernel(int* __restrict__ bsum, int nb) {
    __shared__ int sh[SCAN_B];
    sh[threadIdx.x] = (threadIdx.x < nb) ? bsum[threadIdx.x] : 0;
    __syncthreads();
    #pragma unroll
    for (int o = 1; o < SCAN_B; o <<= 1) {
        int t = (threadIdx.x >= o) ? sh[threadIdx.x - o] : 0;
        __syncthreads();
        sh[threadIdx.x] += t;
        __syncthreads();
    }
    if (threadIdx.x < nb) bsum[threadIdx.x] = sh[threadIdx.x];
}

__global__ void rowptr_kernel(const int* __restrict__ scan,
                              const int* __restrict__ bsum,
                              int* __restrict__ rowptr, int n) {
    int i = blockIdx.x * SCAN_B + threadIdx.x;
    if (i < n) {
        int off = (blockIdx.x > 0) ? bsum[blockIdx.x - 1] : 0;
        rowptr[i + 1] = scan[i] + off;
    }
    if (i == 0) rowptr[0] = 0;
}

// norm computed inline: enorm = dinv[src]*w*dinv[dst]
__global__ void fill_kernel(const int* __restrict__ src,
                            const int* __restrict__ dst,
                            const float* __restrict__ w,
                            const float* __restrict__ dinv,
                            const int* __restrict__ rowptr,
                            int* __restrict__ cur,
                            int* __restrict__ esrc,
                            float* __restrict__ enorm, int e) {
    int i = blockIdx.x * blockDim.x + threadIdx.x;
    if (i < e) {
        int s = src[i];
        int d = dst[i];
        int p = rowptr[d] + atomicAdd(&cur[d], 1);
        esrc[p]  = s;
        enorm[p] = dinv[s] * w[i] * dinv[d];
    }
}

// ---------------- D=128 gather (x4 unroll): aggx = dinv^2*x_i + sum norm*x[src] ----
__global__ __launch_bounds__(256)
void gather0_kernel(const float* __restrict__ x,
                    const int* __restrict__ rowptr,
                    const int* __restrict__ esrc,
                    const float* __restrict__ enorm,
                    const float* __restrict__ dinv,
                    float* __restrict__ out, int n) {
    int node = blockIdx.x * (blockDim.x >> 5) + (threadIdx.x >> 5);
    int lane = threadIdx.x & 31;
    if (node >= n) return;

    const float4* xp = reinterpret_cast<const float4*>(x);
    float s = dinv[node]; s *= s;

    float4 a = xp[(size_t)node * 32 + lane];
    a.x *= s; a.y *= s; a.z *= s; a.w *= s;

    int beg = rowptr[node], end = rowptr[node + 1];
    int e = beg;
    for (; e + 4 <= end; e += 4) {
        int   s0 = esrc[e],     s1 = esrc[e + 1], s2 = esrc[e + 2], s3 = esrc[e + 3];
        float w0 = enorm[e],    w1 = enorm[e + 1];
        float w2 = enorm[e + 2], w3 = enorm[e + 3];
        float4 v0 = xp[(size_t)s0 * 32 + lane];
        float4 v1 = xp[(size_t)s1 * 32 + lane];
        float4 v2 = xp[(size_t)s2 * 32 + lane];
        float4 v3 = xp[(size_t)s3 * 32 + lane];
        a.x += w0 * v0.x; a.y += w0 * v0.y; a.z += w0 * v0.z; a.w += w0 * v0.w;
        a.x += w1 * v1.x; a.y += w1 * v1.y; a.z += w1 * v1.z; a.w += w1 * v1.w;
        a.x += w2 * v2.x; a.y += w2 * v2.y; a.z += w2 * v2.z; a.w += w2 * v2.w;
        a.x += w3 * v3.x; a.y += w3 * v3.y; a.z += w3 * v3.z; a.w += w3 * v3.w;
    }
    for (; e < end; e++) {
        int   si = esrc[e];
        float w  = enorm[e];
        float4 v = xp[(size_t)si * 32 + lane];
        a.x += w * v.x; a.y += w * v.y; a.z += w * v.z; a.w += w * v.w;
    }
    reinterpret_cast<float4*>(out)[(size_t)node * 32 + lane] = a;
}

// ---------------- single-pass TF32 tensor-core GEMM: C = A[M,K] @ B[Ncols,K]^T ----
// Identical machinery to the R10-verified 3xTF32 kernel (fragment layout proven
// correct at rel_err 9.6e-7), minus the low-order correction terms:
// one mma per (mt,nt) instead of three, no Al/Bl arrays (half the smem + cvt).
__device__ __forceinline__ uint32_t tf32_cvt(float x) {
    uint32_t u;
    asm("cvt.rna.tf32.f32 %0, %1;" : "=r"(u) : "f"(x));
    return u;
}

__device__ __forceinline__ void mma_tf32(float* d, const uint32_t* a, const uint32_t* b) {
    asm volatile(
        "mma.sync.aligned.m16n8k8.row.col.f32.tf32.tf32.f32 "
        "{%0,%1,%2,%3},{%4,%5,%6,%7},{%8,%9},{%0,%1,%2,%3};"
        : "+f"(d[0]), "+f"(d[1]), "+f"(d[2]), "+f"(d[3])
        : "r"(a[0]), "r"(a[1]), "r"(a[2]), "r"(a[3]), "r"(b[0]), "r"(b[1]));
}

template<bool BIAS_RELU>
__global__ __launch_bounds__(256)
void gemm_tf32_kernel(const float* __restrict__ A, const float* __restrict__ B,
                      const float* __restrict__ bias,
                      float* __restrict__ C, int M, int Ncols, int K) {
    constexpr int BM = 128, BK = 16;
    // [kt][tile][lane][reg]
    __shared__ uint32_t Ah[2][8][32][4];
    __shared__ uint32_t Bh[2][16][32][2];

    int tid  = threadIdx.x;
    int lane = tid & 31;
    int warp = tid >> 5;
    int wm = (warp >> 1) * 32;       // warp m-offset within block (0,32,64,96)
    int wn = (warp & 1) * 64;        // warp n-offset within block (0,64)
    int block_row = blockIdx.y * BM;
    int block_col = blockIdx.x * 128;

    int ld_row = tid >> 1;           // 0..127
    int c0     = (tid & 1) * 8;      // 0 or 8

    int a_row = block_row + ld_row;
    bool a_ok = a_row < M;
    const float* a_base = A + (size_t)(a_ok ? a_row : 0) * K + c0;
    const float* b_base = B + (size_t)(block_col + ld_row) * K + c0;

    float d[2][8][4];
    #pragma unroll
    for (int i = 0; i < 2; i++)
        #pragma unroll
        for (int j = 0; j < 8; j++)
            #pragma unroll
            for (int r = 0; r < 4; r++) d[i][j][r] = 0.0f;

    int a_mt = ld_row >> 4, a_ml = ld_row & 15;      // writer A tile / local row
    int b_nt = ld_row >> 3, b_nl = ld_row & 7;       // writer B tile / local col

    for (int k0 = 0; k0 < K; k0 += BK) {
        // global loads (overlap with previous compute)
        float4 av0 = make_float4(0.f,0.f,0.f,0.f), av1 = av0;
        if (a_ok) {
            av0 = *reinterpret_cast<const float4*>(a_base + k0);
            av1 = *reinterpret_cast<const float4*>(a_base + k0 + 4);
        }
        float4 bv0 = *reinterpret_cast<const float4*>(b_base + k0);
        float4 bv1 = *reinterpret_cast<const float4*>(b_base + k0 + 4);

        __syncthreads();   // previous compute done: safe to overwrite frags

        // scatter-store A fragments (8 elems, cols c0..c0+7)
        float ae[8] = {av0.x, av0.y, av0.z, av0.w, av1.x, av1.y, av1.z, av1.w};
        #pragma unroll
        for (int j = 0; j < 8; j++) {
            int kk = c0 + j;
            int kt = kk >> 3, k = kk & 7;
            int lw  = ((a_ml & 7) << 2) | (k & 3);
            int reg = ((k & 4) ? 2 : 0) | ((a_ml & 8) ? 1 : 0);
            Ah[kt][a_mt][lw][reg] = tf32_cvt(ae[j]);
        }
        // scatter-store B fragments
        float be[8] = {bv0.x, bv0.y, bv0.z, bv0.w, bv1.x, bv1.y, bv1.z, bv1.w};
        #pragma unroll
        for (int j = 0; j < 8; j++) {
            int kk = c0 + j;
            int kt = kk >> 3, k = kk & 7;
            int lw  = (b_nl << 2) | (k & 3);
            int reg = (k & 4) ? 1 : 0;
            Bh[kt][b_nt][lw][reg] = tf32_cvt(be[j]);
        }
        __syncthreads();

        // compute 2 k-tiles
        #pragma unroll
        for (int kt = 0; kt < 2; kt++) {
            uint32_t ah[2][4], bh[8][2];
            #pragma unroll
            for (int mt = 0; mt < 2; mt++) {
                int m = (wm >> 4) + mt;
                *reinterpret_cast<uint4*>(ah[mt]) = *reinterpret_cast<const uint4*>(Ah[kt][m][lane]);
            }
            #pragma unroll
            for (int nt = 0; nt < 8; nt++) {
                int nn = (wn >> 3) + nt;
                *reinterpret_cast<uint2*>(bh[nt]) = *reinterpret_cast<const uint2*>(Bh[kt][nn][lane]);
            }
            #pragma unroll
            for (int mt = 0; mt < 2; mt++)
                #pragma unroll
                for (int nt = 0; nt < 8; nt++)
                    mma_tf32(d[mt][nt], ah[mt], bh[nt]);
        }
    }

    // epilogue: c0=(g,2c) c1=(g,2c+1) c2=(g+8,2c) c3=(g+8,2c+1)
    int g = lane >> 2, c = lane & 3;
    #pragma unroll
    for (int mt = 0; mt < 2; mt++) {
        int row0 = block_row + wm + mt * 16 + g;
        int row1 = row0 + 8;
        #pragma unroll
        for (int nt = 0; nt < 8; nt++) {
            int col = block_col + wn + nt * 8 + c * 2;
            float v0 = d[mt][nt][0], v1 = d[mt][nt][1];
            float v2 = d[mt][nt][2], v3 = d[mt][nt][3];
            if (BIAS_RELU) {
                float bb0 = bias[col], bb1 = bias[col + 1];
                v0 = fmaxf(v0 + bb0, 0.f); v1 = fmaxf(v1 + bb1, 0.f);
                v2 = fmaxf(v2 + bb0, 0.f); v3 = fmaxf(v3 + bb1, 0.f);
            }
            if (row0 < M)
                *reinterpret_cast<float2*>(C + (size_t)row0 * Ncols + col) = make_float2(v0, v1);
            if (row1 < M)
                *reinterpret_cast<float2*>(C + (size_t)row1 * Ncols + col) = make_float2(v2, v3);
        }
    }
}

// ---------------- layer-2 gather (x4 unroll) + fused LayerNorm ----------------
__global__ __launch_bounds__(256)
void gather2_ln_kernel(const float* __restrict__ h,
                       const int* __restrict__ rowptr,
                       const int* __restrict__ esrc,
                       const float* __restrict__ enorm,
                       const float* __restrict__ dinv,
                       const float* __restrict__ bias,
                       const float* __restrict__ gamma,
                       const float* __restrict__ beta,
                       float* __restrict__ out, int n) {
    int node = blockIdx.x * (blockDim.x >> 5) + (threadIdx.x >> 5);
    int lane = threadIdx.x & 31;
    if (node >= n) return;

    const float4* hp = reinterpret_cast<const float4*>(h);
    float s = dinv[node]; s *= s;

    float4 a = hp[(size_t)node * 32 + lane];
    float4 bv = reinterpret_cast<const float4*>(bias)[lane];
    a.x = a.x * s + bv.x; a.y = a.y * s + bv.y;
    a.z = a.z * s + bv.z; a.w = a.w * s + bv.w;

    int beg = rowptr[node], end = rowptr[node + 1];
    int e = beg;
    for (; e + 4 <= end; e += 4) {
        int   s0 = esrc[e],     s1 = esrc[e + 1], s2 = esrc[e + 2], s3 = esrc[e + 3];
        float w0 = enorm[e],    w1 = enorm[e + 1];
        float w2 = enorm[e + 2], w3 = enorm[e + 3];
        float4 v0 = hp[(size_t)s0 * 32 + lane];
        float4 v1 = hp[(size_t)s1 * 32 + lane];
        float4 v2 = hp[(size_t)s2 * 32 + lane];
        float4 v3 = hp[(size_t)s3 * 32 + lane];
        a.x += w0 * v0.x; a.y += w0 * v0.y; a.z += w0 * v0.z; a.w += w0 * v0.w;
        a.x += w1 * v1.x; a.y += w1 * v1.y; a.z += w1 * v1.z; a.w += w1 * v1.w;
        a.x += w2 * v2.x; a.y += w2 * v2.y; a.z += w2 * v2.z; a.w += w2 * v2.w;
        a.x += w3 * v3.x; a.y += w3 * v3.y; a.z += w3 * v3.z; a.w += w3 * v3.w;
    }
    for (; e < end; e++) {
        int   si = esrc[e];
        float w  = enorm[e];
        float4 v = hp[(size_t)si * 32 + lane];
        a.x += w * v.x; a.y += w * v.y; a.z += w * v.z; a.w += w * v.w;
    }

    float sum = a.x + a.y + a.z + a.w;
    #pragma unroll
    for (int o = 16; o; o >>= 1) sum += __shfl_xor_sync(0xFFFFFFFFu, sum, o);
    float mu = sum * (1.0f / 128.0f);
    float dx = a.x - mu, dy = a.y - mu, dz = a.z - mu, dw = a.w - mu;
    float sq = dx * dx + dy * dy + dz * dz + dw * dw;
    #pragma unroll
    for (int o = 16; o; o >>= 1) sq += __shfl_xor_sync(0xFFFFFFFFu, sq, o);
    float inv = rsqrtf(sq * (1.0f / 128.0f) + 1e-5f);

    float4 gm = reinterpret_cast<const float4*>(gamma)[lane];
    float4 bt = reinterpret_cast<const float4*>(beta)[lane];
    float4 o4;
    o4.x = dx * inv * gm.x + bt.x;
    o4.y = dy * inv * gm.y + bt.y;
    o4.z = dz * inv * gm.z + bt.z;
    o4.w = dw * inv * gm.w + bt.w;
    reinterpret_cast<float4*>(out)[(size_t)node * 32 + lane] = o4;
}

// ---------------- host launcher ----------------
extern "C" void kernel_launch(void* const* d_in, const int* in_sizes, int n_in,
                              void* d_out, int out_size) {
    const float* x     = (const float*)d_in[0];
    const int*   ei    = (const int*)d_in[1];   // int32 (JAX x64 disabled)
    const float* w     = (const float*)d_in[2];
    const float* W1    = (const float*)d_in[3];
    const float* b1    = (const float*)d_in[4];
    const float* W2    = (const float*)d_in[5];
    const float* b2    = (const float*)d_in[6];
    const float* gamma = (const float*)d_in[7];
    const float* beta  = (const float*)d_in[8];
    float*       out   = (float*)d_out;

    const int* src = ei;
    const int* dst = ei + EE;

    float *deg, *dinv, *aggx, *out1, *h2, *enorm;
    int *cnt, *cur, *scan, *bsum, *rowptr, *esrc;
    cudaGetSymbolAddress((void**)&deg,    g_deg);
    cudaGetSymbolAddress((void**)&dinv,   g_dinv);
    cudaGetSymbolAddress((void**)&cnt,    g_cnt);
    cudaGetSymbolAddress((void**)&cur,    g_cur);
    cudaGetSymbolAddress((void**)&scan,   g_scan);
    cudaGetSymbolAddress((void**)&bsum,   g_bsum);
    cudaGetSymbolAddress((void**)&rowptr, g_rowptr);
    cudaGetSymbolAddress((void**)&esrc,   g_esrc);
    cudaGetSymbolAddress((void**)&enorm,  g_enorm);
    cudaGetSymbolAddress((void**)&aggx,   g_aggx);
    cudaGetSymbolAddress((void**)&out1,   g_out1);
    cudaGetSymbolAddress((void**)&h2,     g_h2);

    const int T = 256;

    // normalization coefficients + histogram
    deg_init_kernel<<<(NN + T - 1) / T, T>>>(deg, cnt, cur, NN);
    deg_acc_kernel<<<(EE + T - 1) / T, T>>>(dst, w, deg, cnt, EE);
    dinv_kernel<<<(NN + T - 1) / T, T>>>(deg, dinv, NN);

    // CSR build (sorted by dst), norm fused into fill
    scan_block_kernel<<<NBLK, SCAN_B>>>(cnt, scan, bsum, NN);
    scan_bsum_kernel<<<1, SCAN_B>>>(bsum, NBLK);
    rowptr_kernel<<<NBLK, SCAN_B>>>(scan, bsum, rowptr, NN);
    fill_kernel<<<(EE + T - 1) / T, T>>>(src, dst, w, dinv, rowptr, cur, esrc, enorm, EE);

    // layer 1 (reordered): aggx = S @ x ; out1 = relu(aggx @ W1^T + b1)
    gather0_kernel<<<(NN + 7) / 8, 256>>>(x, rowptr, esrc, enorm, dinv, aggx, NN);
    {
        dim3 grid(DHID / 128, (NN + 127) / 128);
        gemm_tf32_kernel<true><<<grid, 256>>>(aggx, W1, b1, out1, NN, DHID, DIN);
    }

    // layer 2: h2 = out1 @ W2^T ; out = LN(S @ h2 + b2)
    {
        dim3 grid(DIN / 128, (NN + 127) / 128);
        gemm_tf32_kernel<false><<<grid, 256>>>(out1, W2, nullptr, h2, NN, DIN, DHID);
    }
    gather2_ln_kernel<<<(NN + 7) / 8, 256>>>(h2, rowptr, esrc, enorm, dinv, b2, gamma, beta, out, NN);
}